// round 8
// baseline (speedup 1.0000x reference)
#include <cuda_runtime.h>
#include <cuda_bf16.h>
#include <cooperative_groups.h>

namespace cg = cooperative_groups;

#define T_DEC 64
#define TENC  256
#define Bv    32
#define Ev    256
#define Dv    512
#define NMEL  80

// ------------------------------------------------------------------
// Persistent state (ping-pong by step parity)
// ------------------------------------------------------------------
__device__ float g_h[2 * Bv * Dv];     // hidden state h_t  (par = t&1)
__device__ float g_ctx[2 * Bv * Ev];   // attention context ctx_t (par = t&1)

// ------------------------------------------------------------------
// Output heads for one finished step: mel = [ctx,h]@W_mel^T + b, gate likewise.
// 81 rows (80 mel + 1 gate) x 32 batch = 2592 dot products of length 768.
// One warp per (row,b) pair; pairs strided so each CTA keeps b fixed (L1 reuse).
// ------------------------------------------------------------------
__device__ __forceinline__ void heads_for_step(
    const float* __restrict__ ctx, const float* __restrict__ h,
    const float* __restrict__ W_mel, const float* __restrict__ b_mel,
    const float* __restrict__ W_gate, const float* __restrict__ b_gate,
    float* __restrict__ out, int tOut, int bid, int nBlocks)
{
    int lane = threadIdx.x & 31;
    int w = threadIdx.x >> 5;
    for (int p = bid + nBlocks * w; p < 81 * 32; p += nBlocks * 8) {
        int r = p >> 5;      // 0..80
        int b = p & 31;
        const float* wr = (r < 80) ? (W_mel + r * 768) : W_gate;
        const float* cb = ctx + b * Ev;
        const float* hb = h + b * Dv;
        float acc = 0.f;
        #pragma unroll 4
        for (int k = lane; k < 768; k += 32) {
            float dh = (k < 256) ? cb[k] : hb[k - 256];
            acc = fmaf(wr[k], dh, acc);
        }
        #pragma unroll
        for (int o = 16; o; o >>= 1) acc += __shfl_down_sync(0xffffffffu, acc, o);
        if (lane == 0) {
            if (r < 80) out[b * (NMEL * T_DEC) + r * T_DEC + tOut] = acc + b_mel[r];
            else        out[NMEL * T_DEC * Bv + b * T_DEC + tOut] = acc + b_gate[0];
        }
    }
}

// ------------------------------------------------------------------
// K1: attention for step t (+ heads for step t-1).
// 32 clusters of 4 CTAs; cluster = one batch element; CTA q owns e in [q*64, q*64+64).
// SMEM (floats): h[512] proj[64] rZ[64] zp[4*64] u[256*64] twp[256] tw[256]
// ------------------------------------------------------------------
#define K1_SMEM_FLOATS (512 + 64 + 64 + 256 + 256*64 + 256 + 256)
#define K1_SMEM_BYTES  (K1_SMEM_FLOATS * 4)

__global__ void __cluster_dims__(4, 1, 1) k1_attn(
    int t, const float* __restrict__ A, const float* __restrict__ W_att,
    const float* __restrict__ W_mel, const float* __restrict__ b_mel,
    const float* __restrict__ W_gate, const float* __restrict__ b_gate,
    float* __restrict__ out)
{
    extern __shared__ float sm[];
    float* s_h    = sm;             // 512
    float* s_proj = sm + 512;       // 64
    float* s_rZ   = sm + 576;       // 64
    float* s_zp   = sm + 640;       // 256
    float* s_u    = sm + 896;       // 16384  (u[t][e_local], stride 64)
    float* s_twp  = sm + 17280;     // 256
    float* s_tw   = sm + 17536;     // 256

    int tid = threadIdx.x;
    int par = t & 1;
    int b  = blockIdx.x >> 2;
    int q  = blockIdx.x & 3;
    int e0 = q * 64;

    // load h_t for this batch element
    const float* hptr = g_h + par * Bv * Dv + b * Dv;
    for (int i = tid; i < Dv; i += 256) s_h[i] = hptr[i];

    // heads for step t-1 (needs ctx_{t-1} in buffer par^1 and h_t in buffer par)
    if (t > 0) {
        heads_for_step(g_ctx + (par ^ 1) * Bv * Ev, g_h + par * Bv * Dv,
                       W_mel, b_mel, W_gate, b_gate, out, t - 1, blockIdx.x, 128);
    }
    __syncthreads();

    // proj[e] = dot(h, W_att[e,:])  for the 64 owned e's (8 per warp)
    {
        int w = tid >> 5, lane = tid & 31;
        #pragma unroll
        for (int i = 0; i < 8; i++) {
            int el = w * 8 + i;
            const float* wr = W_att + (size_t)(e0 + el) * Dv;
            float acc = 0.f;
            #pragma unroll 4
            for (int k = lane; k < Dv; k += 32) acc = fmaf(wr[k], s_h[k], acc);
            #pragma unroll
            for (int o = 16; o; o >>= 1) acc += __shfl_down_sync(0xffffffffu, acc, o);
            if (lane == 0) s_proj[el] = acc;
        }
    }
    __syncthreads();

    int ee = tid & 63, tt = tid >> 6;
    const float* Abase = A + b * Ev + e0 + ee;   // + ti * (Bv*Ev)
    float p = s_proj[ee];

    // pass 1: u = exp(A*p) (stored once), partial Z per column
    float z = 0.f;
    #pragma unroll 4
    for (int ti = tt; ti < TENC; ti += 4) {
        float a = Abase[ti * (Bv * Ev)];
        float u = __expf(a * p);
        s_u[ti * 64 + ee] = u;
        z += u;
    }
    s_zp[tt * 64 + ee] = z;
    __syncthreads();
    if (tid < 64) {
        float zz = s_zp[tid] + s_zp[64 + tid] + s_zp[128 + tid] + s_zp[192 + tid];
        s_rZ[tid] = 1.f / zz;
    }
    __syncthreads();

    // partial tw[t] = sum over owned e of u/Z  (one warp per 32 t's)
    {
        int w = tid >> 5, lane = tid & 31;
        float rz0 = s_rZ[lane], rz1 = s_rZ[lane + 32];
        for (int ti = w * 32; ti < w * 32 + 32; ti++) {
            float v = s_u[ti * 64 + lane] * rz0 + s_u[ti * 64 + lane + 32] * rz1;
            #pragma unroll
            for (int o = 16; o; o >>= 1) v += __shfl_down_sync(0xffffffffu, v, o);
            if (lane == 0) s_twp[ti] = v;
        }
    }

    cg::cluster_group cl = cg::this_cluster();
    cl.sync();
    // gather full tw across the 4 cluster CTAs via DSMEM
    {
        float s = 0.f;
        #pragma unroll
        for (int r = 0; r < 4; r++) {
            const float* rp = cl.map_shared_rank(s_twp, r);
            s += rp[tid];
        }
        s_tw[tid] = s;
    }
    cl.sync();   // also protects peer SMEM reads vs CTA exit

    // ctx[e] = sum_t tw[t] * A[t,b,e]   (A slice now L1-warm)
    float acc = 0.f;
    #pragma unroll 4
    for (int ti = tt; ti < TENC; ti += 4) {
        acc = fmaf(s_tw[ti], Abase[ti * (Bv * Ev)], acc);
    }
    s_zp[tt * 64 + ee] = acc;
    __syncthreads();
    if (tid < 64) {
        float c = s_zp[tid] + s_zp[64 + tid] + s_zp[128 + tid] + s_zp[192 + tid];
        g_ctx[par * Bv * Ev + b * Ev + e0 + tid] = c;
    }
}

// ------------------------------------------------------------------
// K2: GRU cell for step t. 128 blocks; block j owns d in [j*4, j*4+4).
// Stages x^T, h^T and its 24 weight rows (r,z,n for ih and hh) in SMEM,
// then 192 threads each compute a (row, 4-batch) float4 dot of length 512.
// ------------------------------------------------------------------
#define K2_OFF_WT 0                       // 512*25
#define K2_OFF_XT 12800                   // 512*36
#define K2_OFF_HT 31232                   // 512*36
#define K2_OFF_G  49664                   // 24*32
#define K2_SMEM_FLOATS (49664 + 768)
#define K2_SMEM_BYTES  (K2_SMEM_FLOATS * 4)

__global__ void k2_gru(int t, const float* __restrict__ dec,
                       const float* __restrict__ W_ih,
                       const float* __restrict__ W_hh)
{
    extern __shared__ float sm[];
    float* s_wT = sm + K2_OFF_WT;   // [k][row24], stride 25
    float* s_xT = sm + K2_OFF_XT;   // [k][b], stride 36
    float* s_hT = sm + K2_OFF_HT;   // [k][b], stride 36
    float* s_g  = sm + K2_OFF_G;    // [row24][b]

    int tid = threadIdx.x;
    int par = t & 1;
    int dbase = blockIdx.x * 4;

    // weight slice: rows 0..11 = W_ih(r,z,n x 4d), 12..23 = W_hh
    for (int idx = tid; idx < 24 * 512; idx += 256) {
        int r = idx >> 9, k = idx & 511;
        const float* src;
        if (r < 12) src = W_ih + (size_t)((r >> 2) * Dv + dbase + (r & 3)) * 512 + k;
        else { int rr = r - 12; src = W_hh + (size_t)((rr >> 2) * Dv + dbase + (rr & 3)) * 512 + k; }
        s_wT[k * 25 + r] = *src;
    }
    // x = [dec_{t-1}, ctx_t], transposed
    const float* ctx = g_ctx + par * Bv * Ev;
    for (int idx = tid; idx < Bv * 512; idx += 256) {
        int bb = idx >> 9, k = idx & 511;
        float v;
        if (k < 256) v = (t == 0) ? 0.f : dec[(size_t)(t - 1) * Bv * Ev + bb * Ev + k];
        else         v = ctx[bb * Ev + (k - 256)];
        s_xT[k * 36 + bb] = v;
    }
    // h transposed
    const float* hptr = g_h + par * Bv * Dv;
    for (int idx = tid; idx < Bv * 512; idx += 256) {
        int bb = idx >> 9, k = idx & 511;
        s_hT[k * 36 + bb] = hptr[idx];
    }
    __syncthreads();

    if (tid < 192) {
        int r24 = tid >> 3, bq = tid & 7;
        const float* vbase = ((r24 >= 12) ? s_hT : s_xT) + 4 * bq;
        float4 acc = make_float4(0.f, 0.f, 0.f, 0.f);
        #pragma unroll 8
        for (int k = 0; k < 512; k++) {
            float wv = s_wT[k * 25 + r24];
            float4 v = *reinterpret_cast<const float4*>(vbase + k * 36);
            acc.x = fmaf(wv, v.x, acc.x);
            acc.y = fmaf(wv, v.y, acc.y);
            acc.z = fmaf(wv, v.z, acc.z);
            acc.w = fmaf(wv, v.w, acc.w);
        }
        s_g[r24 * 32 + 4 * bq + 0] = acc.x;
        s_g[r24 * 32 + 4 * bq + 1] = acc.y;
        s_g[r24 * 32 + 4 * bq + 2] = acc.z;
        s_g[r24 * 32 + 4 * bq + 3] = acc.w;
    }
    __syncthreads();

    if (tid < 128) {
        int di = tid >> 5, bb = tid & 31;
        float ir  = s_g[(di     ) * 32 + bb];
        float iz  = s_g[(4  + di) * 32 + bb];
        float inn = s_g[(8  + di) * 32 + bb];
        float hr  = s_g[(12 + di) * 32 + bb];
        float hz  = s_g[(16 + di) * 32 + bb];
        float hn  = s_g[(20 + di) * 32 + bb];
        float r  = 1.f / (1.f + __expf(-(ir + hr)));
        float zz = 1.f / (1.f + __expf(-(iz + hz)));
        float n  = tanhf(inn + r * hn);
        int dg = dbase + di;
        float hold = s_hT[dg * 36 + bb];
        float hnew = fmaxf((1.f - zz) * n + zz * hold, 0.f);
        g_h[(par ^ 1) * Bv * Dv + bb * Dv + dg] = hnew;
    }
}

// ------------------------------------------------------------------
// init: zero h_0 (parity-0 buffer) so every graph replay starts clean
// ------------------------------------------------------------------
__global__ void k_init()
{
    int idx = blockIdx.x * blockDim.x + threadIdx.x;
    if (idx < Bv * Dv) g_h[idx] = 0.f;
}

// heads for the final step (t=63): ctx in buffer 1, h_64 in buffer 0
__global__ void k_heads_final(const float* __restrict__ W_mel,
                              const float* __restrict__ b_mel,
                              const float* __restrict__ W_gate,
                              const float* __restrict__ b_gate,
                              float* __restrict__ out)
{
    heads_for_step(g_ctx + 1 * Bv * Ev, g_h + 0,
                   W_mel, b_mel, W_gate, b_gate, out, 63, blockIdx.x, (int)gridDim.x);
}

// ------------------------------------------------------------------
extern "C" void kernel_launch(void* const* d_in, const int* in_sizes, int n_in,
                              void* d_out, int out_size)
{
    const float* dec    = (const float*)d_in[0];
    const float* A      = (const float*)d_in[1];
    const float* W_att  = (const float*)d_in[2];
    const float* W_ih   = (const float*)d_in[3];
    const float* W_hh   = (const float*)d_in[4];
    const float* W_mel  = (const float*)d_in[5];
    const float* b_mel  = (const float*)d_in[6];
    const float* W_gate = (const float*)d_in[7];
    const float* b_gate = (const float*)d_in[8];
    float* out = (float*)d_out;

    cudaFuncSetAttribute(k1_attn, cudaFuncAttributeMaxDynamicSharedMemorySize, K1_SMEM_BYTES);
    cudaFuncSetAttribute(k2_gru,  cudaFuncAttributeMaxDynamicSharedMemorySize, K2_SMEM_BYTES);

    k_init<<<64, 256>>>();
    for (int t = 0; t < T_DEC; t++) {
        k1_attn<<<128, 256, K1_SMEM_BYTES>>>(t, A, W_att, W_mel, b_mel, W_gate, b_gate, out);
        k2_gru<<<128, 256, K2_SMEM_BYTES>>>(t, dec, W_ih, W_hh);
    }
    k_heads_final<<<96, 256>>>(W_mel, b_mel, W_gate, b_gate, out);
}

// round 9
// speedup vs baseline: 1.3111x; 1.3111x over previous
#include <cuda_runtime.h>
#include <cuda_bf16.h>
#include <cooperative_groups.h>

namespace cg = cooperative_groups;

#define T_DEC 64
#define TENC  256
#define Bv    32
#define Ev    256
#define Dv    512
#define NMEL  80

// ------------------------------------------------------------------
// Persistent state (ping-pong by step parity)
// ------------------------------------------------------------------
__device__ float g_h[2 * Bv * Dv];     // hidden state h_t  (par = t&1)
__device__ float g_ctx[2 * Bv * Ev];   // attention context ctx_t (par = t&1)

// ------------------------------------------------------------------
// Output heads for one finished step: mel = [ctx,h]@W_mel^T + b, gate likewise.
// 2592 dot products of length 768; ~1 per warp across the grid.
// ------------------------------------------------------------------
__device__ __forceinline__ void heads_for_step(
    const float* __restrict__ ctx, const float* __restrict__ h,
    const float* __restrict__ W_mel, const float* __restrict__ b_mel,
    const float* __restrict__ W_gate, const float* __restrict__ b_gate,
    float* __restrict__ out, int tOut, int bid, int nBlocks)
{
    int lane = threadIdx.x & 31;
    int w = threadIdx.x >> 5;
    for (int p = bid + nBlocks * w; p < 81 * 32; p += nBlocks * 8) {
        int r = p >> 5;      // 0..80
        int b = p & 31;
        const float* wr = (r < 80) ? (W_mel + r * 768) : W_gate;
        const float* cb = ctx + b * Ev;
        const float* hb = h + b * Dv;
        float acc = 0.f;
        #pragma unroll 8
        for (int k = lane; k < 768; k += 32) {
            float dh = (k < 256) ? cb[k] : hb[k - 256];
            acc = fmaf(wr[k], dh, acc);
        }
        #pragma unroll
        for (int o = 16; o; o >>= 1) acc += __shfl_down_sync(0xffffffffu, acc, o);
        if (lane == 0) {
            if (r < 80) out[b * (NMEL * T_DEC) + r * T_DEC + tOut] = acc + b_mel[r];
            else        out[NMEL * T_DEC * Bv + b * T_DEC + tOut] = acc + b_gate[0];
        }
    }
}

// ------------------------------------------------------------------
// K1: attention for step t (+ heads for step t-1).
// 32 clusters of 8 CTAs; cluster = one batch element; CTA q owns e in [q*32, q*32+32).
// SMEM floats: h[512] proj[32] rZ[32] zp[256] twp[256] tw[256] u[256*33]
// ------------------------------------------------------------------
#define K1_SMEM_FLOATS (512 + 32 + 32 + 256 + 256 + 256 + 256*33)
#define K1_SMEM_BYTES  (K1_SMEM_FLOATS * 4)

__global__ void __cluster_dims__(8, 1, 1) k1_attn(
    int t, const float* __restrict__ A, const float* __restrict__ W_att,
    const float* __restrict__ W_mel, const float* __restrict__ b_mel,
    const float* __restrict__ W_gate, const float* __restrict__ b_gate,
    float* __restrict__ out)
{
    extern __shared__ float sm[];
    float* s_h    = sm;             // 512
    float* s_proj = sm + 512;       // 32
    float* s_rZ   = sm + 544;       // 32
    float* s_zp   = sm + 576;       // 256
    float* s_twp  = sm + 832;       // 256
    float* s_tw   = sm + 1088;      // 256
    float* s_u    = sm + 1344;      // 256*33 (u[t][e_local], stride 33 -> conflict-free cols)

    int tid = threadIdx.x;
    int par = t & 1;
    int b  = blockIdx.x >> 3;
    int q  = blockIdx.x & 7;
    int e0 = q * 32;

    // load h_t for this batch element
    const float* hptr = g_h + par * Bv * Dv + b * Dv;
    s_h[tid]       = hptr[tid];
    s_h[tid + 256] = hptr[tid + 256];

    // heads for step t-1 (needs ctx_{t-1} in buffer par^1 and h_t in buffer par)
    if (t > 0) {
        heads_for_step(g_ctx + (par ^ 1) * Bv * Ev, g_h + par * Bv * Dv,
                       W_mel, b_mel, W_gate, b_gate, out, t - 1, blockIdx.x, 256);
    }
    __syncthreads();

    // proj[e] = dot(h, W_att[e,:]) for the 32 owned e's.
    // 4 rows per warp with interleaved accumulators -> 16 loads in flight.
    {
        int w = tid >> 5, lane = tid & 31;
        const float* w0 = W_att + (size_t)(e0 + w * 4) * Dv;
        const float* w1 = w0 + Dv;
        const float* w2 = w1 + Dv;
        const float* w3 = w2 + Dv;
        float a0 = 0.f, a1 = 0.f, a2 = 0.f, a3 = 0.f;
        #pragma unroll 4
        for (int k = lane; k < Dv; k += 32) {
            float hv = s_h[k];
            a0 = fmaf(w0[k], hv, a0);
            a1 = fmaf(w1[k], hv, a1);
            a2 = fmaf(w2[k], hv, a2);
            a3 = fmaf(w3[k], hv, a3);
        }
        #pragma unroll
        for (int o = 16; o; o >>= 1) {
            a0 += __shfl_down_sync(0xffffffffu, a0, o);
            a1 += __shfl_down_sync(0xffffffffu, a1, o);
            a2 += __shfl_down_sync(0xffffffffu, a2, o);
            a3 += __shfl_down_sync(0xffffffffu, a3, o);
        }
        if (lane == 0) {
            s_proj[w * 4 + 0] = a0;
            s_proj[w * 4 + 1] = a1;
            s_proj[w * 4 + 2] = a2;
            s_proj[w * 4 + 3] = a3;
        }
    }
    __syncthreads();

    int ee = tid & 31, tt = tid >> 5;
    const float* Abase = A + b * Ev + e0 + ee;   // + ti * (Bv*Ev)
    float p = s_proj[ee];

    // pass 1: u = exp(A*p) stored once, partial Z per e
    float z = 0.f;
    #pragma unroll 8
    for (int ti = tt; ti < TENC; ti += 8) {
        float a = Abase[(size_t)ti * (Bv * Ev)];
        float u = __expf(a * p);
        s_u[ti * 33 + ee] = u;
        z += u;
    }
    s_zp[tid] = z;
    __syncthreads();
    if (tid < 32) {
        float zz = 0.f;
        #pragma unroll
        for (int r = 0; r < 8; r++) zz += s_zp[r * 32 + tid];
        s_rZ[tid] = 1.f / zz;
    }
    __syncthreads();

    // partial tw[t] = sum over owned e of u/Z. lane = local t, loop over e:
    // s_u column access stride 33 -> conflict-free; no shfl chains.
    {
        int ti = (tid >> 5) * 32 + (tid & 31);   // == tid, but keep explicit
        const float* up = s_u + ti * 33;
        float v = 0.f;
        #pragma unroll 8
        for (int e = 0; e < 32; e++) v = fmaf(up[e], s_rZ[e], v);
        s_twp[ti] = v;
    }

    cg::cluster_group cl = cg::this_cluster();
    cl.sync();
    // gather full tw across the 8 cluster CTAs via DSMEM
    {
        float s = 0.f;
        #pragma unroll
        for (int r = 0; r < 8; r++) {
            const float* rp = cl.map_shared_rank(s_twp, r);
            s += rp[tid];
        }
        s_tw[tid] = s;
    }
    cl.sync();   // barrier + protects peer SMEM reads vs CTA exit

    // ctx[e] = sum_t tw[t] * A[t,b,e]   (A slice L1-warm from pass 1)
    float acc = 0.f;
    #pragma unroll 8
    for (int ti = tt; ti < TENC; ti += 8) {
        acc = fmaf(s_tw[ti], Abase[(size_t)ti * (Bv * Ev)], acc);
    }
    s_zp[tid] = acc;
    __syncthreads();
    if (tid < 32) {
        float c = 0.f;
        #pragma unroll
        for (int r = 0; r < 8; r++) c += s_zp[r * 32 + tid];
        g_ctx[par * Bv * Ev + b * Ev + e0 + tid] = c;
    }
}

// ------------------------------------------------------------------
// K2: GRU cell for step t. 128 blocks; block j owns d in [j*4, j*4+4).
// ------------------------------------------------------------------
#define K2_OFF_WT 0                       // 512*25
#define K2_OFF_XT 12800                   // 512*36
#define K2_OFF_HT 31232                   // 512*36
#define K2_OFF_G  49664                   // 24*32
#define K2_SMEM_FLOATS (49664 + 768)
#define K2_SMEM_BYTES  (K2_SMEM_FLOATS * 4)

__global__ void k2_gru(int t, const float* __restrict__ dec,
                       const float* __restrict__ W_ih,
                       const float* __restrict__ W_hh)
{
    extern __shared__ float sm[];
    float* s_wT = sm + K2_OFF_WT;   // [k][row24], stride 25
    float* s_xT = sm + K2_OFF_XT;   // [k][b], stride 36
    float* s_hT = sm + K2_OFF_HT;   // [k][b], stride 36
    float* s_g  = sm + K2_OFF_G;    // [row24][b]

    int tid = threadIdx.x;
    int par = t & 1;
    int dbase = blockIdx.x * 4;

    // weight slice: rows 0..11 = W_ih(r,z,n x 4d), 12..23 = W_hh
    for (int idx = tid; idx < 24 * 512; idx += 256) {
        int r = idx >> 9, k = idx & 511;
        const float* src;
        if (r < 12) src = W_ih + (size_t)((r >> 2) * Dv + dbase + (r & 3)) * 512 + k;
        else { int rr = r - 12; src = W_hh + (size_t)((rr >> 2) * Dv + dbase + (rr & 3)) * 512 + k; }
        s_wT[k * 25 + r] = *src;
    }
    // x = [dec_{t-1}, ctx_t], transposed
    const float* ctx = g_ctx + par * Bv * Ev;
    for (int idx = tid; idx < Bv * 512; idx += 256) {
        int bb = idx >> 9, k = idx & 511;
        float v;
        if (k < 256) v = (t == 0) ? 0.f : dec[(size_t)(t - 1) * Bv * Ev + bb * Ev + k];
        else         v = ctx[bb * Ev + (k - 256)];
        s_xT[k * 36 + bb] = v;
    }
    // h transposed
    const float* hptr = g_h + par * Bv * Dv;
    for (int idx = tid; idx < Bv * 512; idx += 256) {
        int bb = idx >> 9, k = idx & 511;
        s_hT[k * 36 + bb] = hptr[idx];
    }
    __syncthreads();

    if (tid < 192) {
        int r24 = tid >> 3, bq = tid & 7;
        const float* vbase = ((r24 >= 12) ? s_hT : s_xT) + 4 * bq;
        float4 acc = make_float4(0.f, 0.f, 0.f, 0.f);
        #pragma unroll 8
        for (int k = 0; k < 512; k++) {
            float wv = s_wT[k * 25 + r24];
            float4 v = *reinterpret_cast<const float4*>(vbase + k * 36);
            acc.x = fmaf(wv, v.x, acc.x);
            acc.y = fmaf(wv, v.y, acc.y);
            acc.z = fmaf(wv, v.z, acc.z);
            acc.w = fmaf(wv, v.w, acc.w);
        }
        s_g[r24 * 32 + 4 * bq + 0] = acc.x;
        s_g[r24 * 32 + 4 * bq + 1] = acc.y;
        s_g[r24 * 32 + 4 * bq + 2] = acc.z;
        s_g[r24 * 32 + 4 * bq + 3] = acc.w;
    }
    __syncthreads();

    if (tid < 128) {
        int di = tid >> 5, bb = tid & 31;
        float ir  = s_g[(di     ) * 32 + bb];
        float iz  = s_g[(4  + di) * 32 + bb];
        float inn = s_g[(8  + di) * 32 + bb];
        float hr  = s_g[(12 + di) * 32 + bb];
        float hz  = s_g[(16 + di) * 32 + bb];
        float hn  = s_g[(20 + di) * 32 + bb];
        float r  = 1.f / (1.f + __expf(-(ir + hr)));
        float zz = 1.f / (1.f + __expf(-(iz + hz)));
        float n  = tanhf(inn + r * hn);
        int dg = dbase + di;
        float hold = s_hT[dg * 36 + bb];
        float hnew = fmaxf((1.f - zz) * n + zz * hold, 0.f);
        g_h[(par ^ 1) * Bv * Dv + bb * Dv + dg] = hnew;
    }
}

// ------------------------------------------------------------------
// init: zero h_0 (parity-0 buffer) so every graph replay starts clean
// ------------------------------------------------------------------
__global__ void k_init()
{
    int idx = blockIdx.x * blockDim.x + threadIdx.x;
    if (idx < Bv * Dv) g_h[idx] = 0.f;
}

// heads for the final step (t=63): ctx in buffer 1, h_64 in buffer 0
__global__ void k_heads_final(const float* __restrict__ W_mel,
                              const float* __restrict__ b_mel,
                              const float* __restrict__ W_gate,
                              const float* __restrict__ b_gate,
                              float* __restrict__ out)
{
    heads_for_step(g_ctx + 1 * Bv * Ev, g_h + 0,
                   W_mel, b_mel, W_gate, b_gate, out, 63, blockIdx.x, (int)gridDim.x);
}

// ------------------------------------------------------------------
extern "C" void kernel_launch(void* const* d_in, const int* in_sizes, int n_in,
                              void* d_out, int out_size)
{
    const float* dec    = (const float*)d_in[0];
    const float* A      = (const float*)d_in[1];
    const float* W_att  = (const float*)d_in[2];
    const float* W_ih   = (const float*)d_in[3];
    const float* W_hh   = (const float*)d_in[4];
    const float* W_mel  = (const float*)d_in[5];
    const float* b_mel  = (const float*)d_in[6];
    const float* W_gate = (const float*)d_in[7];
    const float* b_gate = (const float*)d_in[8];
    float* out = (float*)d_out;

    cudaFuncSetAttribute(k1_attn, cudaFuncAttributeMaxDynamicSharedMemorySize, K1_SMEM_BYTES);
    cudaFuncSetAttribute(k2_gru,  cudaFuncAttributeMaxDynamicSharedMemorySize, K2_SMEM_BYTES);

    k_init<<<64, 256>>>();
    for (int t = 0; t < T_DEC; t++) {
        k1_attn<<<256, 256, K1_SMEM_BYTES>>>(t, A, W_att, W_mel, b_mel, W_gate, b_gate, out);
        k2_gru<<<128, 256, K2_SMEM_BYTES>>>(t, dec, W_ih, W_hh);
    }
    k_heads_final<<<256, 256>>>(W_mel, b_mel, W_gate, b_gate, out);
}

// round 11
// speedup vs baseline: 2.3114x; 1.7630x over previous
#include <cuda_runtime.h>
#include <cuda_bf16.h>
#include <cooperative_groups.h>

namespace cg = cooperative_groups;

#define T_DEC 64
#define TENC  256
#define Bv    32
#define Ev    256
#define Dv    512
#define NMEL  80
#define NCTA  128
#define NTHR  256

// ------------------------------------------------------------------
// Device-global state
// ------------------------------------------------------------------
__device__ float g_h[2][Bv * Dv];       // h, b-major   (par = t&1 holds h_t)
__device__ float g_hT[2][Dv * Bv];      // h, k-major (transposed)
__device__ float g_ctx[2][Bv * Ev];     // ctx, b-major
__device__ float g_ctxT[2][Ev * Bv];    // ctx, e-major (transposed)
__device__ float g_decT[T_DEC][Ev * Bv];     // dec transposed: [t][e*32+b]
__device__ unsigned g_bar_cnt;               // zero-initialized, returns to 0
__device__ unsigned g_bar_gen;               // monotonic across replays (safe)

// ------------------------------------------------------------------
// Software grid barrier (all 128 CTAs co-resident: grid <= #SMs, 1 CTA/SM)
// ------------------------------------------------------------------
__device__ __forceinline__ void grid_bar()
{
    __syncthreads();
    if (threadIdx.x == 0) {
        __threadfence();
        unsigned gen = *((volatile unsigned*)&g_bar_gen);
        unsigned a = atomicAdd(&g_bar_cnt, 1u);
        if (a == NCTA - 1) {
            g_bar_cnt = 0;
            __threadfence();
            atomicExch(&g_bar_gen, gen + 1u);
        } else {
            while (*((volatile unsigned*)&g_bar_gen) == gen) { __nanosleep(40); }
        }
        __threadfence();
    }
    __syncthreads();
}

// ------------------------------------------------------------------
// SMEM layout (floats). Total 46976 floats = 187,904 B  (< 227 KB, 1 CTA/SM)
// ------------------------------------------------------------------
#define OFF_W    0                    // 24*512 fp32 GRU weight slice (persistent)
#define OFF_A    12288                // 256*64 fp32 A slice (persistent)
#define OFF_U    28672                // 256*65 fp32 softmax u (aliased as s_g in GRU)
#define OFF_CH   45312                // 768: [ctx_prev(256) | h_cur(512)]
#define OFF_PROJ 46080                // 64
#define OFF_RZ   46144                // 64
#define OFF_ZP   46208                // 256
#define OFF_TWP  46464                // 256 (DSMEM-exposed)
#define OFF_TW   46720                // 256
#define SMEM_FLOATS 46976
#define SMEM_BYTES  (SMEM_FLOATS * 4)

// ------------------------------------------------------------------
// Output heads for one step: rows split by cluster-rank q (21/21/21/18)
// ------------------------------------------------------------------
__device__ __forceinline__ void do_heads(
    const float* __restrict__ s_ch,
    const float* __restrict__ W_mel, const float* __restrict__ b_mel,
    const float* __restrict__ W_gate, float gate_b,
    float* __restrict__ out, int tOut, int b, int q, int lane, int wid)
{
    int r0 = q * 21;
    int rend = (q == 3) ? 81 : r0 + 21;
    for (int r = r0 + wid; r < rend; r += 8) {
        const float* wr = (r < 80) ? (W_mel + r * 768) : W_gate;
        float acc = 0.f;
        #pragma unroll 6
        for (int k = lane; k < 768; k += 32) acc = fmaf(wr[k], s_ch[k], acc);
        #pragma unroll
        for (int o = 16; o; o >>= 1) acc += __shfl_down_sync(0xffffffffu, acc, o);
        if (lane == 0) {
            if (r < 80) out[b * (NMEL * T_DEC) + r * T_DEC + tOut] = acc + b_mel[r];
            else        out[NMEL * T_DEC * Bv + b * T_DEC + tOut] = acc + gate_b;
        }
    }
}

// ------------------------------------------------------------------
// The persistent decoder kernel
// ------------------------------------------------------------------
__global__ void __launch_bounds__(NTHR, 1) __cluster_dims__(4, 1, 1)
decoder_persistent(
    const float* __restrict__ dec, const float* __restrict__ A,
    const float* __restrict__ W_att,
    const float* __restrict__ W_ih, const float* __restrict__ W_hh,
    const float* __restrict__ W_mel, const float* __restrict__ b_mel,
    const float* __restrict__ W_gate, const float* __restrict__ b_gate,
    float* __restrict__ out)
{
    extern __shared__ float sm[];
    float* s_W    = sm + OFF_W;
    float* s_A    = sm + OFF_A;     // A slice, fp32, [t*64 + e]
    float* s_u    = sm + OFF_U;     // softmax exp values (stride 65)
    float* s_g    = sm + OFF_U;     // alias: GRU partials (24*8*32)
    float* s_ch   = sm + OFF_CH;
    float* s_proj = sm + OFF_PROJ;
    float* s_rZ   = sm + OFF_RZ;
    float* s_zp   = sm + OFF_ZP;
    float* s_twp  = sm + OFF_TWP;
    float* s_tw   = sm + OFF_TW;

    const int tid  = threadIdx.x;
    const int lane = tid & 31;
    const int wid  = tid >> 5;
    const int cid  = blockIdx.x;
    const int b    = cid >> 2;          // attention role: batch element
    const int q    = cid & 3;           // attention role: e-quadrant
    const int e0   = q * 64;
    const int dbase = cid * 4;          // GRU role: hidden dims [dbase, dbase+4)

    cg::cluster_group cl = cg::this_cluster();
    const float gate_b = b_gate[0];

    // ================= init (once) =================
    // GRU weight slice: rows 0..11 = W_ih gates(r,z,n)x4d, 12..23 = W_hh
    for (int idx = tid; idx < 24 * 512; idx += NTHR) {
        int r = idx >> 9, k = idx & 511;
        const float* src;
        if (r < 12) src = W_ih + (size_t)((r >> 2) * Dv + dbase + (r & 3)) * 512 + k;
        else { int rr = r - 12; src = W_hh + (size_t)((rr >> 2) * Dv + dbase + (rr & 3)) * 512 + k; }
        s_W[idx] = *src;
    }
    // A slice -> fp32 SMEM: s_A[t*64+e] = A[t][b][e0+e]
    for (int idx = tid; idx < TENC * 64; idx += NTHR) {
        int t = idx >> 6, e = idx & 63;
        s_A[idx] = A[(size_t)t * (Bv * Ev) + b * Ev + e0 + e];
    }
    // dec transpose -> g_decT[t][e*32+b]
    for (int idx = cid * NTHR + tid; idx < T_DEC * Bv * Ev; idx += NCTA * NTHR) {
        int t = idx / (Bv * Ev);
        int rem = idx - t * (Bv * Ev);
        int bb = rem >> 8, e = rem & 255;
        g_decT[t][e * Bv + bb] = dec[idx];
    }
    grid_bar();

    // ================= step loop =================
    #pragma unroll 1
    for (int t = 0; t < T_DEC; t++) {
        const int par = t & 1;

        // ---------- Phase A: attention (+ heads for t-1) ----------
        // stage s_ch = [ctx_{t-1}(b) | h_t(b)]
        if (t > 0) {
            for (int i = tid; i < 256; i += NTHR) s_ch[i]       = g_ctx[par ^ 1][b * Ev + i];
            for (int i = tid; i < 512; i += NTHR) s_ch[256 + i] = g_h[par][b * Dv + i];
        } else {
            for (int i = tid; i < 768; i += NTHR) s_ch[i] = 0.f;
        }
        __syncthreads();

        if (t > 0)
            do_heads(s_ch, W_mel, b_mel, W_gate, gate_b, out, t - 1, b, q, lane, wid);

        // proj[e] = h . W_att[e,:] for the 64 owned e's (fp32, float4 loads from L2)
        if (t > 0) {
            const int rbase = e0 + (wid << 3);
            const float4* hp = (const float4*)(s_ch + 256);
            #pragma unroll
            for (int pass = 0; pass < 2; pass++) {
                const float4* w0 = (const float4*)(W_att + (size_t)(rbase + pass * 4 + 0) * Dv);
                const float4* w1 = (const float4*)(W_att + (size_t)(rbase + pass * 4 + 1) * Dv);
                const float4* w2 = (const float4*)(W_att + (size_t)(rbase + pass * 4 + 2) * Dv);
                const float4* w3 = (const float4*)(W_att + (size_t)(rbase + pass * 4 + 3) * Dv);
                float a0 = 0.f, a1 = 0.f, a2 = 0.f, a3 = 0.f;
                #pragma unroll
                for (int k4 = lane; k4 < 128; k4 += 32) {
                    float4 h4 = hp[k4];
                    float4 f0 = w0[k4];
                    float4 f1 = w1[k4];
                    float4 f2 = w2[k4];
                    float4 f3 = w3[k4];
                    a0 = fmaf(f0.x, h4.x, fmaf(f0.y, h4.y, fmaf(f0.z, h4.z, fmaf(f0.w, h4.w, a0))));
                    a1 = fmaf(f1.x, h4.x, fmaf(f1.y, h4.y, fmaf(f1.z, h4.z, fmaf(f1.w, h4.w, a1))));
                    a2 = fmaf(f2.x, h4.x, fmaf(f2.y, h4.y, fmaf(f2.z, h4.z, fmaf(f2.w, h4.w, a2))));
                    a3 = fmaf(f3.x, h4.x, fmaf(f3.y, h4.y, fmaf(f3.z, h4.z, fmaf(f3.w, h4.w, a3))));
                }
                #pragma unroll
                for (int o = 16; o; o >>= 1) {
                    a0 += __shfl_down_sync(0xffffffffu, a0, o);
                    a1 += __shfl_down_sync(0xffffffffu, a1, o);
                    a2 += __shfl_down_sync(0xffffffffu, a2, o);
                    a3 += __shfl_down_sync(0xffffffffu, a3, o);
                }
                if (lane == 0) {
                    int pb = (wid << 3) + pass * 4;
                    s_proj[pb + 0] = a0; s_proj[pb + 1] = a1;
                    s_proj[pb + 2] = a2; s_proj[pb + 3] = a3;
                }
            }
        } else if (tid < 64) s_proj[tid] = 0.f;
        __syncthreads();

        // softmax pass 1: u = exp(a*p), per-e partial Z
        const int ee = tid & 63, tg = tid >> 6;
        {
            float p = s_proj[ee];
            float z = 0.f;
            #pragma unroll 8
            for (int ti = tg; ti < TENC; ti += 4) {
                float a = s_A[ti * 64 + ee];
                float u = __expf(a * p);
                s_u[ti * 65 + ee] = u;
                z += u;
            }
            s_zp[tid] = z;
        }
        __syncthreads();
        if (tid < 64) {
            float zz = s_zp[tid] + s_zp[64 + tid] + s_zp[128 + tid] + s_zp[192 + tid];
            s_rZ[tid] = 1.f / zz;
        }
        __syncthreads();

        // partial tw[t] over owned e's (thread = encoder time index)
        {
            const float* up = s_u + tid * 65;
            float v = 0.f;
            #pragma unroll 8
            for (int e = 0; e < 64; e++) v = fmaf(up[e], s_rZ[e], v);
            s_twp[tid] = v;
        }
        cl.sync();
        {
            float s = 0.f;
            #pragma unroll
            for (int r = 0; r < 4; r++) {
                const float* rp = cl.map_shared_rank(s_twp, r);
                s += rp[tid];
            }
            s_tw[tid] = s;
        }
        cl.sync();

        // ctx[e] = sum_t tw[t] * a[t,e]
        {
            float acc = 0.f;
            #pragma unroll 8
            for (int ti = tg; ti < TENC; ti += 4)
                acc = fmaf(s_tw[ti], s_A[ti * 64 + ee], acc);
            s_zp[tid] = acc;
        }
        __syncthreads();
        if (tid < 64) {
            float c = s_zp[tid] + s_zp[64 + tid] + s_zp[128 + tid] + s_zp[192 + tid];
            g_ctx[par][b * Ev + e0 + tid] = c;
            g_ctxT[par][(e0 + tid) * Bv + b] = c;
        }
        grid_bar();

        // ---------- Phase B: GRU (d-parallel, weights SMEM-resident) ----------
        {
            const int kbase = wid * 64;
            float acc[24];
            #pragma unroll
            for (int r = 0; r < 24; r++) acc[r] = 0.f;

            const bool xz = (t == 0) && (kbase < 256);
            const bool hz = (t == 0);
            const float* xsrc = (kbase < 256)
                ? (g_decT[(t > 0) ? (t - 1) : 0] + kbase * Bv)
                : (g_ctxT[par] + (kbase - 256) * Bv);
            const float* hsrc = g_hT[par] + kbase * Bv;

            #pragma unroll 2
            for (int kk = 0; kk < 64; kk += 4) {
                float xv0 = xz ? 0.f : xsrc[(kk + 0) * Bv + lane];
                float xv1 = xz ? 0.f : xsrc[(kk + 1) * Bv + lane];
                float xv2 = xz ? 0.f : xsrc[(kk + 2) * Bv + lane];
                float xv3 = xz ? 0.f : xsrc[(kk + 3) * Bv + lane];
                float hv0 = hz ? 0.f : hsrc[(kk + 0) * Bv + lane];
                float hv1 = hz ? 0.f : hsrc[(kk + 1) * Bv + lane];
                float hv2 = hz ? 0.f : hsrc[(kk + 2) * Bv + lane];
                float hv3 = hz ? 0.f : hsrc[(kk + 3) * Bv + lane];
                #pragma unroll
                for (int r = 0; r < 12; r++) {
                    float4 w = *(const float4*)(s_W + r * 512 + kbase + kk);
                    acc[r] = fmaf(w.x, xv0, acc[r]);
                    acc[r] = fmaf(w.y, xv1, acc[r]);
                    acc[r] = fmaf(w.z, xv2, acc[r]);
                    acc[r] = fmaf(w.w, xv3, acc[r]);
                }
                #pragma unroll
                for (int r = 12; r < 24; r++) {
                    float4 w = *(const float4*)(s_W + r * 512 + kbase + kk);
                    acc[r] = fmaf(w.x, hv0, acc[r]);
                    acc[r] = fmaf(w.y, hv1, acc[r]);
                    acc[r] = fmaf(w.z, hv2, acc[r]);
                    acc[r] = fmaf(w.w, hv3, acc[r]);
                }
            }
            __syncthreads();   // s_g aliases s_u: phase A fully done (grid_bar passed)
            #pragma unroll
            for (int r = 0; r < 24; r++) s_g[(r * 8 + wid) * 32 + lane] = acc[r];
        }
        __syncthreads();

        if (tid < 128) {
            const int dl = tid >> 5, bb = tid & 31;
            float G[6];
            #pragma unroll
            for (int g = 0; g < 6; g++) {
                int r = (g % 3) * 4 + dl + ((g >= 3) ? 12 : 0);
                float s = 0.f;
                #pragma unroll
                for (int w = 0; w < 8; w++) s += s_g[(r * 8 + w) * 32 + bb];
                G[g] = s;
            }
            float rg = 1.f / (1.f + __expf(-(G[0] + G[3])));
            float zg = 1.f / (1.f + __expf(-(G[1] + G[4])));
            float ng = tanhf(G[2] + rg * G[5]);
            float hold = (t == 0) ? 0.f : g_hT[par][(dbase + dl) * Bv + bb];
            float hnew = fmaxf((1.f - zg) * ng + zg * hold, 0.f);
            g_hT[par ^ 1][(dbase + dl) * Bv + bb] = hnew;
            g_h[par ^ 1][bb * Dv + dbase + dl]    = hnew;
        }
        grid_bar();
    }

    // ---------- final heads (t = 63): ctx_63 in g_ctx[1], h_64 in g_h[0] ----------
    for (int i = tid; i < 256; i += NTHR) s_ch[i]       = g_ctx[1][b * Ev + i];
    for (int i = tid; i < 512; i += NTHR) s_ch[256 + i] = g_h[0][b * Dv + i];
    __syncthreads();
    do_heads(s_ch, W_mel, b_mel, W_gate, gate_b, out, 63, b, q, lane, wid);
}

// ------------------------------------------------------------------
extern "C" void kernel_launch(void* const* d_in, const int* in_sizes, int n_in,
                              void* d_out, int out_size)
{
    const float* dec    = (const float*)d_in[0];
    const float* A      = (const float*)d_in[1];
    const float* W_att  = (const float*)d_in[2];
    const float* W_ih   = (const float*)d_in[3];
    const float* W_hh   = (const float*)d_in[4];
    const float* W_mel  = (const float*)d_in[5];
    const float* b_mel  = (const float*)d_in[6];
    const float* W_gate = (const float*)d_in[7];
    const float* b_gate = (const float*)d_in[8];
    float* out = (float*)d_out;

    cudaFuncSetAttribute(decoder_persistent,
                         cudaFuncAttributeMaxDynamicSharedMemorySize, SMEM_BYTES);

    decoder_persistent<<<NCTA, NTHR, SMEM_BYTES>>>(
        dec, A, W_att, W_ih, W_hh, W_mel, b_mel, W_gate, b_gate, out);
}

// round 12
// speedup vs baseline: 2.6874x; 1.1626x over previous
#include <cuda_runtime.h>
#include <cuda_bf16.h>
#include <cooperative_groups.h>

namespace cg = cooperative_groups;

#define T_DEC 64
#define TENC  256
#define Bv    32
#define Ev    256
#define Dv    512
#define NMEL  80
#define NCTA  128
#define NTHR  256

// ------------------------------------------------------------------
// Device-global state
// ------------------------------------------------------------------
__device__ float g_hT[2][Dv * Bv];           // h ping-pong, k-major (GRU input)
__device__ float g_ctxT[2][Ev * Bv];         // ctx ping-pong, e-major (GRU input)
__device__ float g_hHist[T_DEC + 1][Bv * Dv];   // h_t history, b-major (proj + heads)
__device__ float g_ctxHist[T_DEC][Bv * Ev];     // ctx_t history, b-major (heads)
__device__ float g_decT[T_DEC][Ev * Bv];        // dec transposed: [t][e*32+b]
__device__ unsigned g_bar_cnt;               // returns to 0 each barrier
__device__ unsigned g_bar_gen;               // monotonic across replays (safe)

// ------------------------------------------------------------------
// f32x2 packed helpers (sm_103a FFMA2 path)
// ------------------------------------------------------------------
__device__ __forceinline__ unsigned long long pk2(float lo, float hi) {
    unsigned long long v;
    asm("mov.b64 %0, {%1,%2};" : "=l"(v) : "f"(lo), "f"(hi));
    return v;
}
__device__ __forceinline__ unsigned long long f2fma(
    unsigned long long a, unsigned long long b, unsigned long long c) {
    unsigned long long d;
    asm("fma.rn.f32x2 %0, %1, %2, %3;" : "=l"(d) : "l"(a), "l"(b), "l"(c));
    return d;
}
__device__ __forceinline__ float upk_sum(unsigned long long v) {
    float lo, hi;
    asm("mov.b64 {%0,%1}, %2;" : "=f"(lo), "=f"(hi) : "l"(v));
    return lo + hi;
}
__device__ __forceinline__ float fast_exp2(float x) {
    float y;
    asm("ex2.approx.ftz.f32 %0, %1;" : "=f"(y) : "f"(x));
    return y;
}

// ------------------------------------------------------------------
// Hierarchical grid barrier: cluster.sync fan-in, 32 leader atomics.
// ------------------------------------------------------------------
__device__ __forceinline__ void grid_bar(cg::cluster_group& cl, bool lead)
{
    __threadfence();         // publish this thread's writes gpu-wide
    cl.sync();               // intra-cluster fan-in
    if (lead) {
        unsigned gen = *((volatile unsigned*)&g_bar_gen);
        unsigned a = atomicAdd(&g_bar_cnt, 1u);
        if (a == 31) {
            g_bar_cnt = 0;
            __threadfence();
            atomicExch(&g_bar_gen, gen + 1u);
        } else {
            while (*((volatile unsigned*)&g_bar_gen) == gen) {}
        }
    }
    cl.sync();               // release peers
    __threadfence();         // acquire side
}

// ------------------------------------------------------------------
// SMEM layout (floats). 46720 floats = 186,880 B (< 227 KB, 1 CTA/SM)
// ------------------------------------------------------------------
#define OFF_W    0          // 24*512 GRU weight slice (persistent through loop)
#define OFF_A    12288      // 256*64 A slice, pre-scaled by log2(e) (persistent)
#define OFF_U    28672      // 256*65 softmax u  (aliased: s_g GRU partials, s_P heads)
#define OFF_H    45312      // 512 h staging
#define OFF_PROJ 45824      // 64
#define OFF_RZ   45888      // 64
#define OFF_ZP   45952      // 256
#define OFF_TWP  46208      // 256 (DSMEM-exposed)
#define OFF_TW   46464      // 256
#define SMEM_FLOATS 46720
#define SMEM_BYTES  (SMEM_FLOATS * 4)

#define LOG2E 1.442695040888963f
#define LN2   0.693147180559945f

// ------------------------------------------------------------------
// The persistent decoder kernel
// ------------------------------------------------------------------
__global__ void __launch_bounds__(NTHR, 1) __cluster_dims__(4, 1, 1)
decoder_persistent(
    const float* __restrict__ dec, const float* __restrict__ A,
    const float* __restrict__ W_att,
    const float* __restrict__ W_ih, const float* __restrict__ W_hh,
    const float* __restrict__ W_mel, const float* __restrict__ b_mel,
    const float* __restrict__ W_gate, const float* __restrict__ b_gate,
    float* __restrict__ out)
{
    extern __shared__ float sm[];
    float* s_W    = sm + OFF_W;
    float* s_A    = sm + OFF_A;     // A slice * log2e, [t*64 + e]
    float* s_u    = sm + OFF_U;     // softmax exp values (stride 65)
    float* s_g    = sm + OFF_U;     // alias: GRU partials (24*8*32)
    float* s_h    = sm + OFF_H;
    float* s_proj = sm + OFF_PROJ;
    float* s_rZ   = sm + OFF_RZ;
    float* s_zp   = sm + OFF_ZP;
    float* s_twp  = sm + OFF_TWP;
    float* s_tw   = sm + OFF_TW;

    const int tid  = threadIdx.x;
    const int lane = tid & 31;
    const int wid  = tid >> 5;
    const int cid  = blockIdx.x;
    const int b    = cid >> 2;          // attention role: batch element
    const int q    = cid & 3;           // attention role: e-quadrant
    const int e0   = q * 64;
    const int dbase = cid * 4;          // GRU role: hidden dims [dbase, dbase+4)

    cg::cluster_group cl = cg::this_cluster();
    const bool lead = (q == 0) && (tid == 0);
    const float gate_b = b_gate[0];

    // ================= init (once) =================
    // GRU weight slice: rows 0..11 = W_ih gates(r,z,n)x4d, 12..23 = W_hh
    for (int idx = tid; idx < 24 * 512; idx += NTHR) {
        int r = idx >> 9, k = idx & 511;
        const float* src;
        if (r < 12) src = W_ih + (size_t)((r >> 2) * Dv + dbase + (r & 3)) * 512 + k;
        else { int rr = r - 12; src = W_hh + (size_t)((rr >> 2) * Dv + dbase + (rr & 3)) * 512 + k; }
        s_W[idx] = *src;
    }
    // A slice (pre-scaled by log2e): s_A[t*64+e] = A[t][b][e0+e] * LOG2E
    for (int idx = tid; idx < TENC * 64; idx += NTHR) {
        int t = idx >> 6, e = idx & 63;
        s_A[idx] = A[(size_t)t * (Bv * Ev) + b * Ev + e0 + e] * LOG2E;
    }
    // dec transpose -> g_decT[t][e*32+b]
    for (int idx = cid * NTHR + tid; idx < T_DEC * Bv * Ev; idx += NCTA * NTHR) {
        int t = idx / (Bv * Ev);
        int rem = idx - t * (Bv * Ev);
        int bb = rem >> 8, e = rem & 255;
        g_decT[t][e * Bv + bb] = dec[idx];
    }
    grid_bar(cl, lead);

    // ================= step loop =================
    #pragma unroll 1
    for (int t = 0; t < T_DEC; t++) {
        const int par = t & 1;

        // ---------- Phase A: attention ----------
        if (t > 0) {
            const float* hptr = g_hHist[t] + b * Dv;
            s_h[tid]       = hptr[tid];
            s_h[tid + 256] = hptr[tid + 256];
        } else {
            s_h[tid] = 0.f; s_h[tid + 256] = 0.f;
        }
        __syncthreads();

        // proj[e] = h . W_att[e,:] for the 64 owned e's (fp32 float4 from L2)
        if (t > 0) {
            const int rbase = e0 + (wid << 3);
            const float4* hp = (const float4*)s_h;
            #pragma unroll
            for (int pass = 0; pass < 2; pass++) {
                const float4* w0 = (const float4*)(W_att + (size_t)(rbase + pass * 4 + 0) * Dv);
                const float4* w1 = (const float4*)(W_att + (size_t)(rbase + pass * 4 + 1) * Dv);
                const float4* w2 = (const float4*)(W_att + (size_t)(rbase + pass * 4 + 2) * Dv);
                const float4* w3 = (const float4*)(W_att + (size_t)(rbase + pass * 4 + 3) * Dv);
                float a0 = 0.f, a1 = 0.f, a2 = 0.f, a3 = 0.f;
                #pragma unroll
                for (int k4 = lane; k4 < 128; k4 += 32) {
                    float4 h4 = hp[k4];
                    float4 f0 = w0[k4];
                    float4 f1 = w1[k4];
                    float4 f2 = w2[k4];
                    float4 f3 = w3[k4];
                    a0 = fmaf(f0.x, h4.x, fmaf(f0.y, h4.y, fmaf(f0.z, h4.z, fmaf(f0.w, h4.w, a0))));
                    a1 = fmaf(f1.x, h4.x, fmaf(f1.y, h4.y, fmaf(f1.z, h4.z, fmaf(f1.w, h4.w, a1))));
                    a2 = fmaf(f2.x, h4.x, fmaf(f2.y, h4.y, fmaf(f2.z, h4.z, fmaf(f2.w, h4.w, a2))));
                    a3 = fmaf(f3.x, h4.x, fmaf(f3.y, h4.y, fmaf(f3.z, h4.z, fmaf(f3.w, h4.w, a3))));
                }
                #pragma unroll
                for (int o = 16; o; o >>= 1) {
                    a0 += __shfl_down_sync(0xffffffffu, a0, o);
                    a1 += __shfl_down_sync(0xffffffffu, a1, o);
                    a2 += __shfl_down_sync(0xffffffffu, a2, o);
                    a3 += __shfl_down_sync(0xffffffffu, a3, o);
                }
                if (lane == 0) {
                    int pb = (wid << 3) + pass * 4;
                    s_proj[pb + 0] = a0; s_proj[pb + 1] = a1;
                    s_proj[pb + 2] = a2; s_proj[pb + 3] = a3;
                }
            }
        } else if (tid < 64) s_proj[tid] = 0.f;
        __syncthreads();

        // softmax pass 1: u = exp2(a'*p)  (a' = a*log2e), per-e partial Z
        const int ee = tid & 63, tg = tid >> 6;
        {
            float p = s_proj[ee];
            float z = 0.f;
            #pragma unroll 8
            for (int ti = tg; ti < TENC; ti += 4) {
                float a = s_A[ti * 64 + ee];
                float u = fast_exp2(a * p);
                s_u[ti * 65 + ee] = u;
                z += u;
            }
            s_zp[tid] = z;
        }
        __syncthreads();
        if (tid < 64) {
            float zz = s_zp[tid] + s_zp[64 + tid] + s_zp[128 + tid] + s_zp[192 + tid];
            s_rZ[tid] = 1.f / zz;
        }
        __syncthreads();

        // partial tw[t] over owned e's (thread = encoder time index)
        {
            const float* up = s_u + tid * 65;
            float v = 0.f;
            #pragma unroll 8
            for (int e = 0; e < 64; e++) v = fmaf(up[e], s_rZ[e], v);
            s_twp[tid] = v;
        }
        cl.sync();
        {
            float s = 0.f;
            #pragma unroll
            for (int r = 0; r < 4; r++) {
                const float* rp = cl.map_shared_rank(s_twp, r);
                s += rp[tid];
            }
            s_tw[tid] = s;
        }
        cl.sync();

        // ctx[e] = ln2 * sum_t tw[t] * a'[t,e]   (a' = a*log2e)
        {
            float acc = 0.f;
            #pragma unroll 8
            for (int ti = tg; ti < TENC; ti += 4)
                acc = fmaf(s_tw[ti], s_A[ti * 64 + ee], acc);
            s_zp[tid] = acc;
        }
        __syncthreads();
        if (tid < 64) {
            float c = (s_zp[tid] + s_zp[64 + tid] + s_zp[128 + tid] + s_zp[192 + tid]) * LN2;
            g_ctxHist[t][b * Ev + e0 + tid] = c;
            g_ctxT[par][(e0 + tid) * Bv + b] = c;
        }
        grid_bar(cl, lead);

        // ---------- Phase B: GRU (d-parallel, packed f32x2 FMA) ----------
        {
            const int kbase = wid * 64;
            unsigned long long acc2[24];
            #pragma unroll
            for (int r = 0; r < 24; r++) acc2[r] = 0ull;

            const bool xz = (t == 0) && (kbase < 256);
            const bool hz = (t == 0);
            const float* xsrc = (kbase < 256)
                ? (g_decT[(t > 0) ? (t - 1) : 0] + kbase * Bv)
                : (g_ctxT[par] + (kbase - 256) * Bv);
            const float* hsrc = g_hT[par] + kbase * Bv;

            #pragma unroll 4
            for (int kk = 0; kk < 64; kk += 4) {
                float x0 = xz ? 0.f : xsrc[(kk + 0) * Bv + lane];
                float x1 = xz ? 0.f : xsrc[(kk + 1) * Bv + lane];
                float x2 = xz ? 0.f : xsrc[(kk + 2) * Bv + lane];
                float x3 = xz ? 0.f : xsrc[(kk + 3) * Bv + lane];
                float h0 = hz ? 0.f : hsrc[(kk + 0) * Bv + lane];
                float h1 = hz ? 0.f : hsrc[(kk + 1) * Bv + lane];
                float h2 = hz ? 0.f : hsrc[(kk + 2) * Bv + lane];
                float h3 = hz ? 0.f : hsrc[(kk + 3) * Bv + lane];
                unsigned long long px01 = pk2(x0, x1), px23 = pk2(x2, x3);
                unsigned long long ph01 = pk2(h0, h1), ph23 = pk2(h2, h3);
                #pragma unroll
                for (int r = 0; r < 12; r++) {
                    ulonglong2 wp = *(const ulonglong2*)(s_W + r * 512 + kbase + kk);
                    acc2[r] = f2fma(wp.x, px01, acc2[r]);
                    acc2[r] = f2fma(wp.y, px23, acc2[r]);
                }
                #pragma unroll
                for (int r = 12; r < 24; r++) {
                    ulonglong2 wp = *(const ulonglong2*)(s_W + r * 512 + kbase + kk);
                    acc2[r] = f2fma(wp.x, ph01, acc2[r]);
                    acc2[r] = f2fma(wp.y, ph23, acc2[r]);
                }
            }
            #pragma unroll
            for (int r = 0; r < 24; r++)
                s_g[(r * 8 + wid) * 32 + lane] = upk_sum(acc2[r]);
        }
        __syncthreads();

        if (tid < 128) {
            const int dl = tid >> 5, bb = tid & 31;
            float G[6];
            #pragma unroll
            for (int g = 0; g < 6; g++) {
                int r = (g % 3) * 4 + dl + ((g >= 3) ? 12 : 0);
                float s = 0.f;
                #pragma unroll
                for (int w = 0; w < 8; w++) s += s_g[(r * 8 + w) * 32 + bb];
                G[g] = s;
            }
            float rg = 1.f / (1.f + __expf(-(G[0] + G[3])));
            float zg = 1.f / (1.f + __expf(-(G[1] + G[4])));
            float ng = tanhf(G[2] + rg * G[5]);
            float hold = (t == 0) ? 0.f : g_hT[par][(dbase + dl) * Bv + bb];
            float hnew = fmaxf((1.f - zg) * ng + zg * hold, 0.f);
            g_hT[par ^ 1][(dbase + dl) * Bv + bb] = hnew;
            g_hHist[t + 1][bb * Dv + dbase + dl] = hnew;
        }
        grid_bar(cl, lead);
    }

    // ================= final heads pass =================
    // CTA covers 16 (t,b) pairs: pid = cid*16+p -> t = pid>>5, b = pid&31.
    // All 16 pairs share one t; b in [b0, b0+16).
    {
        float* s_WC = sm;               // 27*768 = 20736 floats (over s_W + s_A)
        float* s_P  = sm + OFF_U;       // 16*772 = 12352 floats (over s_u)
        const int tP = (cid * 16) >> 5;
        const int b0 = (cid * 16) & 31;

        // stage the 16 input vectors [ctx_t | h_{t+1}]
        for (int idx = tid; idx < 16 * 768; idx += NTHR) {
            int p = idx / 768, i = idx - p * 768;
            int bb = b0 + p;
            float v = (i < 256) ? g_ctxHist[tP][bb * Ev + i]
                                : g_hHist[tP + 1][bb * Dv + (i - 256)];
            s_P[p * 772 + i] = v;
        }
        __syncthreads();

        #pragma unroll 1
        for (int chunk = 0; chunk < 3; chunk++) {
            const int r0 = chunk * 27;
            for (int idx = tid; idx < 27 * 768; idx += NTHR) {
                int j = idx / 768, k = idx - j * 768;
                int rg = r0 + j;
                s_WC[idx] = (rg < 80) ? W_mel[(size_t)rg * 768 + k] : W_gate[k];
            }
            __syncthreads();

            for (int d = tid; d < 27 * 16; d += NTHR) {
                int j = d >> 4, p = d & 15;
                const float4* wr = (const float4*)(s_WC + j * 768);
                const float4* ch = (const float4*)(s_P + p * 772);
                float acc = 0.f;
                #pragma unroll 8
                for (int k4 = 0; k4 < 192; k4++) {
                    float4 w = wr[k4];
                    float4 c = ch[k4];
                    acc = fmaf(w.x, c.x, fmaf(w.y, c.y, fmaf(w.z, c.z, fmaf(w.w, c.w, acc))));
                }
                int rg = r0 + j;
                int bb = b0 + p;
                if (rg < 80) out[bb * (NMEL * T_DEC) + rg * T_DEC + tP] = acc + b_mel[rg];
                else         out[NMEL * T_DEC * Bv + bb * T_DEC + tP]   = acc + gate_b;
            }
            __syncthreads();
        }
    }
}

// ------------------------------------------------------------------
extern "C" void kernel_launch(void* const* d_in, const int* in_sizes, int n_in,
                              void* d_out, int out_size)
{
    const float* dec    = (const float*)d_in[0];
    const float* A      = (const float*)d_in[1];
    const float* W_att  = (const float*)d_in[2];
    const float* W_ih   = (const float*)d_in[3];
    const float* W_hh   = (const float*)d_in[4];
    const float* W_mel  = (const float*)d_in[5];
    const float* b_mel  = (const float*)d_in[6];
    const float* W_gate = (const float*)d_in[7];
    const float* b_gate = (const float*)d_in[8];
    float* out = (float*)d_out;

    cudaFuncSetAttribute(decoder_persistent,
                         cudaFuncAttributeMaxDynamicSharedMemorySize, SMEM_BYTES);

    decoder_persistent<<<NCTA, NTHR, SMEM_BYTES>>>(
        dec, A, W_att, W_ih, W_hh, W_mel, b_mel, W_gate, b_gate, out);
}

// round 13
// speedup vs baseline: 3.2107x; 1.1947x over previous
#include <cuda_runtime.h>
#include <cuda_bf16.h>
#include <cooperative_groups.h>

namespace cg = cooperative_groups;

#define T_DEC 64
#define TENC  256
#define Bv    32
#define Ev    256
#define Dv    512
#define NMEL  80
#define NCTA  128
#define NGRID 148
#define NTHR  256

// ------------------------------------------------------------------
// Device-global state
// ------------------------------------------------------------------
__device__ float g_hT[2][Dv * Bv];            // h ping-pong, k-major (GRU input)
__device__ float g_ctxT[2][Ev * Bv];          // ctx ping-pong, e-major (GRU input)
__device__ float g_hHist[T_DEC + 1][Bv * Dv]; // h_t history, b-major (proj + heads)
__device__ float g_ctxHist[T_DEC][Bv * Ev];   // ctx_t history, b-major (heads)
__device__ float g_decT[T_DEC][Ev * Bv];      // dec transposed: [t][e*32+b]
__device__ unsigned g_bar_cnt;                // returns to 0 each barrier
__device__ unsigned g_bar_gen;                // monotonic across replays (safe)

// ------------------------------------------------------------------
// f32x2 packed helpers (sm_103a FFMA2 path)
// ------------------------------------------------------------------
__device__ __forceinline__ unsigned long long pk2(float lo, float hi) {
    unsigned long long v;
    asm("mov.b64 %0, {%1,%2};" : "=l"(v) : "f"(lo), "f"(hi));
    return v;
}
__device__ __forceinline__ unsigned long long f2fma(
    unsigned long long a, unsigned long long b, unsigned long long c) {
    unsigned long long d;
    asm("fma.rn.f32x2 %0, %1, %2, %3;" : "=l"(d) : "l"(a), "l"(b), "l"(c));
    return d;
}
__device__ __forceinline__ float upk_sum(unsigned long long v) {
    float lo, hi;
    asm("mov.b64 {%0,%1}, %2;" : "=f"(lo), "=f"(hi) : "l"(v));
    return lo + hi;
}
__device__ __forceinline__ float fast_exp2(float x) {
    float y;
    asm("ex2.approx.ftz.f32 %0, %1;" : "=f"(y) : "f"(x));
    return y;
}

// ------------------------------------------------------------------
// Hierarchical grid barrier: cluster.sync fan-in, 32 leader atomics.
// ------------------------------------------------------------------
__device__ __forceinline__ void grid_bar(cg::cluster_group& cl, bool lead)
{
    __threadfence();
    cl.sync();
    if (lead) {
        unsigned gen = *((volatile unsigned*)&g_bar_gen);
        unsigned a = atomicAdd(&g_bar_cnt, 1u);
        if (a == 31) {
            g_bar_cnt = 0;
            __threadfence();
            atomicExch(&g_bar_gen, gen + 1u);
        } else {
            while (*((volatile unsigned*)&g_bar_gen) == gen) {}
        }
    }
    cl.sync();
    __threadfence();
}

// ------------------------------------------------------------------
// SMEM layout (floats). 57984 floats = 231,936 B  (<= 232,448 max dyn)
// ------------------------------------------------------------------
#define OFF_WGRU 0          // 96*128  GRU weight slice (16 dims x 6 gates, k-quarter)
#define OFF_A    12288      // 256*65  A slice * log2e, padded stride 65
#define OFF_WATT 28928      // 64*384  W_att e-slice, cols 0..383
#define OFF_GP   53504      // 96*32   GRU partials (DSMEM-exposed)
#define OFF_H    56576      // 512     h staging
#define OFF_PROJ 57088      // 64
#define OFF_RZ   57152      // 64
#define OFF_ZP   57216      // 256
#define OFF_TWP  57472      // 256  (DSMEM-exposed)
#define OFF_TW   57728      // 256
#define SMEM_FLOATS 57984
#define SMEM_BYTES  (SMEM_FLOATS * 4)

#define LOG2E 1.442695040888963f
#define LN2   0.693147180559945f

// ------------------------------------------------------------------
// The persistent decoder kernel
// ------------------------------------------------------------------
__global__ void __launch_bounds__(NTHR, 1) __cluster_dims__(4, 1, 1)
decoder_persistent(
    const float* __restrict__ dec, const float* __restrict__ A,
    const float* __restrict__ W_att,
    const float* __restrict__ W_ih, const float* __restrict__ W_hh,
    const float* __restrict__ W_mel, const float* __restrict__ b_mel,
    const float* __restrict__ W_gate, const float* __restrict__ b_gate,
    float* __restrict__ out)
{
    if (blockIdx.x >= NCTA) return;   // grid padded to 148 for full-chip issue

    extern __shared__ float sm[];
    float* s_Wg   = sm + OFF_WGRU;
    float* s_A    = sm + OFF_A;
    float* s_Wa   = sm + OFF_WATT;
    float* s_gp   = sm + OFF_GP;
    float* s_h    = sm + OFF_H;
    float* s_proj = sm + OFF_PROJ;
    float* s_rZ   = sm + OFF_RZ;
    float* s_zp   = sm + OFF_ZP;
    float* s_twp  = sm + OFF_TWP;
    float* s_tw   = sm + OFF_TW;

    const int tid  = threadIdx.x;
    const int lane = tid & 31;
    const int wid  = tid >> 5;
    const int cid  = blockIdx.x;
    const int b    = cid >> 2;          // attention: batch element (== cluster id)
    const int q    = cid & 3;           // attention: e-quadrant / GRU: k-quarter
    const int e0   = q * 64;

    cg::cluster_group cl = cg::this_cluster();
    const bool lead = (q == 0) && (tid == 0);
    const float gate_b = b_gate[0];

    // ================= init (once) =================
    // GRU weights: row r = g*16+dl (g: 0..2 ih r/z/n, 3..5 hh r/z/n), k-quarter q
    {
        float4* dst = (float4*)s_Wg;
        for (int idx = tid; idx < 96 * 32; idx += NTHR) {
            int r = idx >> 5, c4 = idx & 31;
            int g = r >> 4, dl = r & 15;
            int d = (b << 4) + dl;
            const float* src = (g < 3)
                ? (W_ih + ((size_t)g * Dv + d) * 512)
                : (W_hh + ((size_t)(g - 3) * Dv + d) * 512);
            dst[idx] = ((const float4*)(src + q * 128))[c4];
        }
    }
    // A slice * log2e, padded stride 65
    for (int idx = tid; idx < TENC * 64; idx += NTHR) {
        int tt = idx >> 6, e = idx & 63;
        s_A[tt * 65 + e] = A[(size_t)tt * (Bv * Ev) + b * Ev + e0 + e] * LOG2E;
    }
    // W_att e-slice, cols 0..383 resident
    {
        float4* dst = (float4*)s_Wa;
        for (int idx = tid; idx < 64 * 96; idx += NTHR) {
            int row = idx / 96, c4 = idx - row * 96;
            dst[row * 96 + c4] = ((const float4*)(W_att + (size_t)(e0 + row) * Dv))[c4];
        }
    }
    // dec transpose -> g_decT[t][e*32+b]
    for (int idx = cid * NTHR + tid; idx < T_DEC * Bv * Ev; idx += NCTA * NTHR) {
        int t = idx / (Bv * Ev);
        int rem = idx - t * (Bv * Ev);
        int bb = rem >> 8, e = rem & 255;
        g_decT[t][e * Bv + bb] = dec[idx];
    }
    grid_bar(cl, lead);

    // ================= step loop =================
    #pragma unroll 1
    for (int t = 0; t < T_DEC; t++) {
        const int par = t & 1;

        // ---------- Phase A: attention ----------
        if (t > 0) {
            const float* hptr = g_hHist[t] + b * Dv;
            s_h[tid]       = hptr[tid];
            s_h[tid + 256] = hptr[tid + 256];
        }
        __syncthreads();

        // proj[e] = h . W_att[e,:]: cols 0..383 from SMEM, 384..511 from L2
        if (t > 0) {
            const float4* hp = (const float4*)s_h;
            #pragma unroll
            for (int pass = 0; pass < 2; pass++) {
                const int rl = (wid << 3) + pass * 4;     // local e row
                const float4* s0 = (const float4*)(s_Wa + (rl + 0) * 384);
                const float4* s1 = (const float4*)(s_Wa + (rl + 1) * 384);
                const float4* s2 = (const float4*)(s_Wa + (rl + 2) * 384);
                const float4* s3 = (const float4*)(s_Wa + (rl + 3) * 384);
                const float4* g0 = (const float4*)(W_att + (size_t)(e0 + rl + 0) * Dv + 384);
                const float4* g1 = (const float4*)(W_att + (size_t)(e0 + rl + 1) * Dv + 384);
                const float4* g2 = (const float4*)(W_att + (size_t)(e0 + rl + 2) * Dv + 384);
                const float4* g3 = (const float4*)(W_att + (size_t)(e0 + rl + 3) * Dv + 384);
                float a0 = 0.f, a1 = 0.f, a2 = 0.f, a3 = 0.f;
                #pragma unroll
                for (int i = 0; i < 3; i++) {
                    int k4 = lane + 32 * i;
                    float4 h4 = hp[k4];
                    float4 f0 = s0[k4], f1 = s1[k4], f2 = s2[k4], f3 = s3[k4];
                    a0 = fmaf(f0.x, h4.x, fmaf(f0.y, h4.y, fmaf(f0.z, h4.z, fmaf(f0.w, h4.w, a0))));
                    a1 = fmaf(f1.x, h4.x, fmaf(f1.y, h4.y, fmaf(f1.z, h4.z, fmaf(f1.w, h4.w, a1))));
                    a2 = fmaf(f2.x, h4.x, fmaf(f2.y, h4.y, fmaf(f2.z, h4.z, fmaf(f2.w, h4.w, a2))));
                    a3 = fmaf(f3.x, h4.x, fmaf(f3.y, h4.y, fmaf(f3.z, h4.z, fmaf(f3.w, h4.w, a3))));
                }
                {
                    float4 h4 = hp[lane + 96];
                    float4 f0 = g0[lane], f1 = g1[lane], f2 = g2[lane], f3 = g3[lane];
                    a0 = fmaf(f0.x, h4.x, fmaf(f0.y, h4.y, fmaf(f0.z, h4.z, fmaf(f0.w, h4.w, a0))));
                    a1 = fmaf(f1.x, h4.x, fmaf(f1.y, h4.y, fmaf(f1.z, h4.z, fmaf(f1.w, h4.w, a1))));
                    a2 = fmaf(f2.x, h4.x, fmaf(f2.y, h4.y, fmaf(f2.z, h4.z, fmaf(f2.w, h4.w, a2))));
                    a3 = fmaf(f3.x, h4.x, fmaf(f3.y, h4.y, fmaf(f3.z, h4.z, fmaf(f3.w, h4.w, a3))));
                }
                #pragma unroll
                for (int o = 16; o; o >>= 1) {
                    a0 += __shfl_down_sync(0xffffffffu, a0, o);
                    a1 += __shfl_down_sync(0xffffffffu, a1, o);
                    a2 += __shfl_down_sync(0xffffffffu, a2, o);
                    a3 += __shfl_down_sync(0xffffffffu, a3, o);
                }
                if (lane == 0) {
                    s_proj[rl + 0] = a0; s_proj[rl + 1] = a1;
                    s_proj[rl + 2] = a2; s_proj[rl + 3] = a3;
                }
            }
        } else if (tid < 64) s_proj[tid] = 0.f;
        __syncthreads();

        // softmax pass 1: Z[e] partials (u recomputed later; not stored)
        const int ee = tid & 63, tg = tid >> 6;
        {
            float p = s_proj[ee];
            float z = 0.f;
            #pragma unroll 8
            for (int ti = tg; ti < TENC; ti += 4)
                z += fast_exp2(s_A[ti * 65 + ee] * p);
            s_zp[tid] = z;
        }
        __syncthreads();
        if (tid < 64) {
            float zz = s_zp[tid] + s_zp[64 + tid] + s_zp[128 + tid] + s_zp[192 + tid];
            s_rZ[tid] = 1.f / zz;
        }
        __syncthreads();

        // tw[t] partial over owned e's (thread = encoder time index); u recomputed
        {
            const float* ap = s_A + tid * 65;
            float v = 0.f;
            #pragma unroll 8
            for (int e = 0; e < 64; e++) {
                float u = fast_exp2(ap[e] * s_proj[e]);
                v = fmaf(u, s_rZ[e], v);
            }
            s_twp[tid] = v;
        }
        cl.sync();
        {
            float s = 0.f;
            #pragma unroll
            for (int r = 0; r < 4; r++) {
                const float* rp = cl.map_shared_rank(s_twp, r);
                s += rp[tid];
            }
            s_tw[tid] = s;
        }
        cl.sync();

        // ctx[e] = ln2 * sum_t tw[t] * a'[t,e]
        {
            float acc = 0.f;
            #pragma unroll 8
            for (int ti = tg; ti < TENC; ti += 4)
                acc = fmaf(s_tw[ti], s_A[ti * 65 + ee], acc);
            s_zp[tid] = acc;
        }
        __syncthreads();
        if (tid < 64) {
            float c = (s_zp[tid] + s_zp[64 + tid] + s_zp[128 + tid] + s_zp[192 + tid]) * LN2;
            g_ctxHist[t][b * Ev + e0 + tid] = c;
            g_ctxT[par][(e0 + tid) * Bv + b] = c;
        }
        grid_bar(cl, lead);

        // ---------- Phase B: GRU (cluster owns 16 dims, CTA owns k-quarter) ----------
        float psum[24];
        {
            const int rg = wid & 3;           // row-group: 0,1 -> x rows; 2,3 -> h rows
            const int kh = wid >> 2;          // k-half within this CTA's 128-k range
            const int r0 = rg * 24;
            const int kabs0 = q * 128 + kh * 64;

            bool zsrc = false;
            const float* src;
            if (rg < 2) {
                if (kabs0 < 256) {
                    zsrc = (t == 0);
                    src = g_decT[(t > 0) ? (t - 1) : 0] + kabs0 * Bv;
                } else {
                    src = g_ctxT[par] + (kabs0 - 256) * Bv;
                }
            } else {
                zsrc = (t == 0);
                src = g_hT[par] + kabs0 * Bv;
            }

            unsigned long long acc2[24];
            #pragma unroll
            for (int j = 0; j < 24; j++) acc2[j] = 0ull;

            const float* wbase = s_Wg + r0 * 128 + kh * 64;
            #pragma unroll 2
            for (int kk = 0; kk < 64; kk += 4) {
                float v0 = zsrc ? 0.f : src[(kk + 0) * Bv + lane];
                float v1 = zsrc ? 0.f : src[(kk + 1) * Bv + lane];
                float v2 = zsrc ? 0.f : src[(kk + 2) * Bv + lane];
                float v3 = zsrc ? 0.f : src[(kk + 3) * Bv + lane];
                unsigned long long p01 = pk2(v0, v1), p23 = pk2(v2, v3);
                #pragma unroll
                for (int j = 0; j < 24; j++) {
                    ulonglong2 wp = *(const ulonglong2*)(wbase + j * 128 + kk);
                    acc2[j] = f2fma(wp.x, p01, acc2[j]);
                    acc2[j] = f2fma(wp.y, p23, acc2[j]);
                }
            }
            #pragma unroll
            for (int j = 0; j < 24; j++) psum[j] = upk_sum(acc2[j]);

            // merge the two k-halves into s_gp
            if (wid < 4) {
                #pragma unroll
                for (int j = 0; j < 24; j++) s_gp[(r0 + j) * 32 + lane] = psum[j];
            }
        }
        __syncthreads();
        if (wid >= 4) {
            const int r0 = (wid & 3) * 24;
            #pragma unroll
            for (int j = 0; j < 24; j++) s_gp[(r0 + j) * 32 + lane] += psum[j];
        }
        cl.sync();   // also covers __syncthreads for the add above

        // epilogue: CTA q handles local dims [4q, 4q+4)
        if (tid < 128) {
            const int dl = q * 4 + (tid >> 5);
            const int bb = lane;
            float G[6];
            #pragma unroll
            for (int g = 0; g < 6; g++) {
                float s = 0.f;
                #pragma unroll
                for (int r = 0; r < 4; r++) {
                    const float* rp = cl.map_shared_rank(s_gp, r);
                    s += rp[(g * 16 + dl) * 32 + bb];
                }
                G[g] = s;
            }
            float rg = 1.f / (1.f + __expf(-(G[0] + G[3])));
            float zg = 1.f / (1.f + __expf(-(G[1] + G[4])));
            float ng = tanhf(G[2] + rg * G[5]);
            int d = (b << 4) + dl;
            float hold = (t == 0) ? 0.f : g_hT[par][d * Bv + bb];
            float hnew = fmaxf((1.f - zg) * ng + zg * hold, 0.f);
            g_hT[par ^ 1][d * Bv + bb] = hnew;
            g_hHist[t + 1][bb * Dv + d] = hnew;
        }
        grid_bar(cl, lead);
    }

    // ================= final heads pass =================
    // CTA covers 16 (t,b) pairs sharing one t: tP = cid/2, b in [b0, b0+16)
    {
        float* s_WC = sm;               // 27*768 floats (over s_Wg + s_A head)
        float* s_P  = sm + 20736;       // 16*772 floats
        const int tP = cid >> 1;
        const int b0 = (cid & 1) * 16;

        for (int idx = tid; idx < 16 * 768; idx += NTHR) {
            int p = idx / 768, i = idx - p * 768;
            int bb = b0 + p;
            float v = (i < 256) ? g_ctxHist[tP][bb * Ev + i]
                                : g_hHist[tP + 1][bb * Dv + (i - 256)];
            s_P[p * 772 + i] = v;
        }
        __syncthreads();

        #pragma unroll 1
        for (int chunk = 0; chunk < 3; chunk++) {
            const int r0 = chunk * 27;
            for (int idx = tid; idx < 27 * 768; idx += NTHR) {
                int j = idx / 768, k = idx - j * 768;
                int rg = r0 + j;
                s_WC[idx] = (rg < 80) ? W_mel[(size_t)rg * 768 + k] : W_gate[k];
            }
            __syncthreads();

            for (int d = tid; d < 27 * 16; d += NTHR) {
                int j = d >> 4, p = d & 15;
                const float4* wr = (const float4*)(s_WC + j * 768);
                const float4* ch = (const float4*)(s_P + p * 772);
                float acc = 0.f;
                #pragma unroll 8
                for (int k4 = 0; k4 < 192; k4++) {
                    float4 w = wr[k4];
                    float4 c = ch[k4];
                    acc = fmaf(w.x, c.x, fmaf(w.y, c.y, fmaf(w.z, c.z, fmaf(w.w, c.w, acc))));
                }
                int rg = r0 + j;
                int bb = b0 + p;
                if (rg < 80) out[bb * (NMEL * T_DEC) + rg * T_DEC + tP] = acc + b_mel[rg];
                else         out[NMEL * T_DEC * Bv + bb * T_DEC + tP]   = acc + gate_b;
            }
            __syncthreads();
        }
    }
}

// ------------------------------------------------------------------
extern "C" void kernel_launch(void* const* d_in, const int* in_sizes, int n_in,
                              void* d_out, int out_size)
{
    const float* dec    = (const float*)d_in[0];
    const float* A      = (const float*)d_in[1];
    const float* W_att  = (const float*)d_in[2];
    const float* W_ih   = (const float*)d_in[3];
    const float* W_hh   = (const float*)d_in[4];
    const float* W_mel  = (const float*)d_in[5];
    const float* b_mel  = (const float*)d_in[6];
    const float* W_gate = (const float*)d_in[7];
    const float* b_gate = (const float*)d_in[8];
    float* out = (float*)d_out;

    cudaFuncSetAttribute(decoder_persistent,
                         cudaFuncAttributeMaxDynamicSharedMemorySize, SMEM_BYTES);

    decoder_persistent<<<NGRID, NTHR, SMEM_BYTES>>>(
        dec, A, W_att, W_ih, W_hh, W_mel, b_mel, W_gate, b_gate, out);
}